// round 5
// baseline (speedup 1.0000x reference)
#include <cuda_runtime.h>
#include <cstdint>

// HardNegativeMining: per-row top-128 of logits with the one-hot positive
// boosted to rank 0. Output = concat(out_logits[B,128], out_labels[B,128]).
//
// R4: half-row work units (grid 2B) for finer drain-tail granularity; the
// last-arriving half-CTA of each row sorts that row's candidates (collected
// in __device__ global scratch). __ldcs evict-first streaming loads.

#define N_CAND   100000
#define HALF     50000
#define K_OUT    128
#define THREADS  512
#define CAP      512        // row candidate cap: mean ~347, sd ~19
#define SORT_P   512
#define NBINS    2048
#define T1       2.7f
#define ROWS_MAX 4096

__device__ unsigned long long g_cand[ROWS_MAX * CAP];   // 16.8 MB scratch
__device__ int   g_cnt[ROWS_MAX];
__device__ int   g_done[ROWS_MAX];
__device__ int   g_pos[ROWS_MAX];
__device__ float g_posval[ROWS_MAX];

__device__ __forceinline__ unsigned int f2k(float f) {
    unsigned int u = __float_as_uint(f);
    return (u & 0x80000000u) ? ~u : (u | 0x80000000u);
}
__device__ __forceinline__ float k2f(unsigned int k) {
    unsigned int u = (k & 0x80000000u) ? (k & 0x7FFFFFFFu) : ~k;
    return __uint_as_float(u);
}
__device__ __forceinline__ unsigned long long pack(unsigned int key, int idx) {
    // high 32: orderable key. low 32: ~idx so equal keys rank smaller index
    // first under the descending read-out (JAX tie-break).
    return ((unsigned long long)key << 32) | (unsigned int)(~idx);
}

struct SRow {
    unsigned long long cand[SORT_P];   // 4 KB
    unsigned int hist[NBINS];          // 8 KB (fallback only)
    int   cnt;
    int   ofs;
    int   last;
    int   binthr;
};

__global__ void hnm_init(int nrows) {
    int i = blockIdx.x * blockDim.x + threadIdx.x;
    if (i < nrows) {
        g_cnt[i] = 0;
        g_done[i] = 0;
        g_pos[i] = -1;
        g_posval[i] = 0.0f;
    }
}

__device__ __forceinline__ void handle4(const float4& x, const float4& l,
                                        int gbase, int row, SRow* s) {
    unsigned int lb = __float_as_uint(l.x) | __float_as_uint(l.y)
                    | __float_as_uint(l.z) | __float_as_uint(l.w);
    float mx = fmaxf(fmaxf(x.x, x.y), fmaxf(x.z, x.w));
    if (__builtin_expect((lb == 0u) & (mx <= T1), 1)) return;

    const float xs[4] = {x.x, x.y, x.z, x.w};
    const float ls[4] = {l.x, l.y, l.z, l.w};
    #pragma unroll
    for (int c = 0; c < 4; c++) {
        if (ls[c] != 0.0f) {
            g_pos[row] = gbase + c;
            g_posval[row] = xs[c];
            int p = atomicAdd(&s->cnt, 1);
            if (p < SORT_P) s->cand[p] = pack(0xFFFFFFFFu, gbase + c);
        } else if (xs[c] > T1) {
            int p = atomicAdd(&s->cnt, 1);
            if (p < SORT_P) s->cand[p] = pack(f2k(xs[c]), gbase + c);
        }
    }
}

__global__ __launch_bounds__(THREADS, 4)
void hnm_scan_sort(const float* __restrict__ logits,
                   const float* __restrict__ labels,
                   float* __restrict__ out_logits,
                   float* __restrict__ out_labels) {
    __shared__ SRow s;

    const int unit = blockIdx.x;
    const int row  = unit >> 1;
    const int half = unit & 1;
    const int tid  = threadIdx.x;

    if (tid == 0) s.cnt = 0;
    __syncthreads();

    // ---- Streaming pass over this half-row (the mandatory DRAM traffic)
    {
        const int gofs = half * HALF;                 // element offset in row
        const float4* lg4 = reinterpret_cast<const float4*>(
            logits + (size_t)row * N_CAND + gofs);
        const float4* lb4 = reinterpret_cast<const float4*>(
            labels + (size_t)row * N_CAND + gofs);
        const int NV = HALF / 4;                      // 12500

        int v = tid;
        for (; v + THREADS < NV; v += 2 * THREADS) {
            float4 xa = __ldcs(lg4 + v);
            float4 xb = __ldcs(lg4 + v + THREADS);
            float4 la = __ldcs(lb4 + v);
            float4 lb = __ldcs(lb4 + v + THREADS);
            handle4(xa, la, gofs + v * 4, row, &s);
            handle4(xb, lb, gofs + (v + THREADS) * 4, row, &s);
        }
        for (; v < NV; v += THREADS) {
            float4 x = __ldcs(lg4 + v);
            float4 l = __ldcs(lb4 + v);
            handle4(x, l, gofs + v * 4, row, &s);
        }
    }
    __syncthreads();

    // ---- Publish candidates to the row's global scratch
    const int n_true = s.cnt;
    const int n = min(n_true, SORT_P);
    if (tid == 0) s.ofs = atomicAdd(&g_cnt[row], n_true);
    __syncthreads();
    {
        int base = row * CAP;
        int ofs = s.ofs;
        for (int i = tid; i < n; i += THREADS) {
            int o = ofs + i;
            if (o < CAP) g_cand[base + o] = s.cand[i];
        }
    }
    __syncthreads();
    __threadfence();

    if (tid == 0) s.last = (atomicAdd(&g_done[row], 1) == 1);
    __syncthreads();
    if (!s.last) return;

    // ---- This CTA is the last for the row: sort & emit
    __threadfence();   // acquire side of the ticket handshake

    int cnt = *((volatile int*)&g_cnt[row]);
    int pos = *((volatile int*)&g_pos[row]);
    float posval = *((volatile float*)&g_posval[row]);

    unsigned long long r;
    if (cnt >= K_OUT && cnt <= CAP) {
        r = (tid < cnt) ? g_cand[row * CAP + tid] : 0ull;
    } else {
        // ---- Fallback: exact coarse histogram threshold over the full row
        //      (correctness guard; never taken for N(0,1) inputs).
        for (int b = tid; b < NBINS; b += THREADS) s.hist[b] = 0;
        if (tid == 0) s.cnt = 0;
        __syncthreads();

        const float4* lg4 = reinterpret_cast<const float4*>(
            logits + (size_t)row * N_CAND);
        const int NV = N_CAND / 4;
        for (int w = tid; w < NV; w += THREADS) {
            float4 x = lg4[w];
            int base = w * 4;
            float xs[4] = {x.x, x.y, x.z, x.w};
            #pragma unroll
            for (int c = 0; c < 4; c++) {
                unsigned int k = (base + c == pos) ? 0xFFFFFFFFu : f2k(xs[c]);
                atomicAdd(&s.hist[k >> 21], 1u);
            }
        }
        __syncthreads();

        if (tid == 0) {
            unsigned int acc = 0; int b = NBINS - 1;
            for (; b > 0; b--) { acc += s.hist[b]; if (acc >= K_OUT) break; }
            s.binthr = b;
        }
        __syncthreads();

        unsigned int kth = (unsigned int)s.binthr << 21;
        for (int w = tid; w < NV; w += THREADS) {
            float4 x = lg4[w];
            int base = w * 4;
            float xs[4] = {x.x, x.y, x.z, x.w};
            #pragma unroll
            for (int c = 0; c < 4; c++) {
                unsigned int k = (base + c == pos) ? 0xFFFFFFFFu : f2k(xs[c]);
                if (k >= kth) {
                    int p = atomicAdd(&s.cnt, 1);
                    if (p < SORT_P) s.cand[p] = pack(k, base + c);
                }
            }
        }
        __syncthreads();
        int fcnt = min(s.cnt, SORT_P);
        r = (tid < fcnt) ? s.cand[tid] : 0ull;
        __syncthreads();
    }

    // ---- Hybrid bitonic sort: 512 elements, 1/thread.
    //      j < 32 -> shfl (no barrier); j >= 32 -> smem exchange.
    #pragma unroll
    for (int k = 2; k <= SORT_P; k <<= 1) {
        #pragma unroll
        for (int j = k >> 1; j > 0; j >>= 1) {
            unsigned long long other;
            if (j >= 32) {
                __syncthreads();
                s.cand[tid] = r;
                __syncthreads();
                other = s.cand[tid ^ j];
            } else {
                other = __shfl_xor_sync(0xFFFFFFFFu, r, j);
            }
            bool lower = (tid & j) == 0;
            bool up    = (tid & k) == 0;
            unsigned long long mn = (r < other) ? r : other;
            unsigned long long mx = (r < other) ? other : r;
            r = (lower == up) ? mn : mx;
        }
    }
    __syncthreads();
    s.cand[tid] = r;
    __syncthreads();

    // ---- Emit top-128 descending; values reconstructed bit-exactly.
    if (tid < K_OUT) {
        unsigned long long e = s.cand[SORT_P - 1 - tid];
        unsigned int key = (unsigned int)(e >> 32);
        float val, lab;
        if (key == 0xFFFFFFFFu) { val = posval; lab = 1.0f; }
        else                    { val = k2f(key); lab = 0.0f; }
        out_logits[(size_t)row * K_OUT + tid] = val;
        out_labels[(size_t)row * K_OUT + tid] = lab;
    }
}

extern "C" void kernel_launch(void* const* d_in, const int* in_sizes, int n_in,
                              void* d_out, int out_size) {
    const float* logits = (const float*)d_in[0];
    const float* labels = (const float*)d_in[1];
    const int B = in_sizes[0] / N_CAND;   // 2048
    float* out_logits = (float*)d_out;
    float* out_labels = out_logits + (size_t)B * K_OUT;

    hnm_init<<<(B + 255) / 256, 256>>>(B);
    hnm_scan_sort<<<2 * B, THREADS>>>(logits, labels, out_logits, out_labels);
}